// round 4
// baseline (speedup 1.0000x reference)
#include <cuda_runtime.h>
#include <cuda_fp16.h>

#define N_ENTITY 500000
#define N_REL    32
#define DIM      64
#define NHOP     2
#define N_ITEM   10000
#define N_MEM    32
#define BATCH    4096
#define HIST     50

// Static scratch (allocation-free):
__device__ float g_acc[N_ITEM * DIM];       // 2.56 MB: per-item accumulated embedding
__device__ float g_ph[N_ENTITY];            // 2 MB: entity_emb . w_h
__device__ float g_pt[N_ENTITY];            // 2 MB: entity_emb . w_t
__device__ float g_pr[N_REL];               // relation projections
__device__ uint2 g_eth[N_ENTITY * 16];      // 64 MB: fp16 copy of entity table
                                            // (row = 16 x uint2 = 64 halfs)

__device__ __forceinline__ float warp_sum32(float v) {
    #pragma unroll
    for (int off = 16; off > 0; off >>= 1)
        v += __shfl_xor_sync(0xffffffffu, v, off);
    return v;
}

__device__ __forceinline__ float half_sum16(float v) {
    #pragma unroll
    for (int off = 1; off < 16; off <<= 1)
        v += __shfl_xor_sync(0xffffffffu, v, off);
    return v;
}

// ---------------------------------------------------------------------------
// K0: single streaming pass over the entity table.
// Per row: scalar projections (w_h, w_t) AND fp16 compressed copy.
// Halfwarp (16 lanes, float4) per row; coalesced 256B reads, 128B writes.
// ---------------------------------------------------------------------------
__global__ __launch_bounds__(256, 8)
void project_kernel(const float* __restrict__ entity_emb,
                    const float* __restrict__ relation_emb,
                    const float* __restrict__ W_w)
{
    const int tid  = blockIdx.x * 256 + threadIdx.x;
    const int hw   = tid >> 4;
    const int ll   = tid & 15;
    const int n_hw = (gridDim.x * 256) >> 4;

    const float4 wh = reinterpret_cast<const float4*>(W_w)[ll];
    const float4 wt = reinterpret_cast<const float4*>(W_w)[32 + ll];

    for (int e = hw; e < N_ENTITY; e += n_hw) {
        const float4 v = reinterpret_cast<const float4*>(entity_emb)[e * (DIM / 4) + ll];

        // fp16 compressed row (this is what K1 gathers)
        const __half2 h01 = __floats2half2_rn(v.x, v.y);
        const __half2 h23 = __floats2half2_rn(v.z, v.w);
        uint2 packed;
        packed.x = *reinterpret_cast<const unsigned int*>(&h01);
        packed.y = *reinterpret_cast<const unsigned int*>(&h23);
        g_eth[e * 16 + ll] = packed;

        float sh = v.x * wh.x + v.y * wh.y + v.z * wh.z + v.w * wh.w;
        float st = v.x * wt.x + v.y * wt.y + v.z * wt.z + v.w * wt.w;
        #pragma unroll
        for (int off = 1; off < 16; off <<= 1) {
            sh += __shfl_xor_sync(0xffffffffu, sh, off);
            st += __shfl_xor_sync(0xffffffffu, st, off);
        }
        if (ll == 0) { g_ph[e] = sh; g_pt[e] = st; }
    }

    // Relation projections: warp 0 of block 0.
    if (blockIdx.x == 0 && threadIdx.x < 32) {
        const float4 wr = reinterpret_cast<const float4*>(W_w)[16 + ll];
        const int half = threadIdx.x >> 4;
        for (int r = half; r < N_REL; r += 2) {
            const float4 v = reinterpret_cast<const float4*>(relation_emb)[r * (DIM / 4) + ll];
            float s = v.x * wr.x + v.y * wr.y + v.z * wr.z + v.w * wr.w;
            #pragma unroll
            for (int off = 1; off < 16; off <<= 1)
                s += __shfl_xor_sync(0xffffffffu, s, off);
            if (ll == 0) g_pr[r] = s;
        }
    }
}

// ---------------------------------------------------------------------------
// K1: per-item attention, both hops fused.
// Phase A: 64 threads compute all 64 logits from L2-resident scalar gathers.
// Phase B: 8 warps gather the 64 fp16 tail rows (128B each, LDG.64 per lane
//          pair layout) from the L2-resident compressed table.
// ---------------------------------------------------------------------------
__global__ __launch_bounds__(256, 8)
void item_acc_kernel(const float* __restrict__ entity_emb,
                     const float* __restrict__ W_b,
                     const int*   __restrict__ item_ids,
                     const int*   __restrict__ heads,
                     const int*   __restrict__ relations,
                     const int*   __restrict__ tails)
{
    const int item = blockIdx.x;
    const int tid  = threadIdx.x;
    const int w    = tid >> 5;
    const int lane = tid & 31;
    const int half = lane >> 4;
    const int ll   = lane & 15;

    __shared__ float ev_s[2 * N_MEM];
    __shared__ int   st_s[2 * N_MEM];
    __shared__ float acc_s[DIM];
    __shared__ float denom_s[2];

    // Phase A: logits for all 64 memories + base embedding load.
    if (tid < 64) {
        const int hop = tid >> 5, mm = tid & 31;
        const int off = (hop * N_ITEM + item) * N_MEM + mm;
        const int hi = heads[off];
        const int ri = relations[off];
        const int ti = tails[off];
        st_s[tid] = ti;
        const float logit = g_ph[hi] + g_pr[ri] + g_pt[ti] + W_b[0];
        const float sg = 1.0f / (1.0f + expf(-logit));
        ev_s[tid] = expf(sg);     // softmax numerator; sg in (0,1), no max-sub needed
        acc_s[tid] = entity_emb[(long long)item_ids[item] * DIM + tid];
    }
    __syncthreads();

    // Per-hop softmax denominators.
    if (tid < 64) {
        float v = warp_sum32(ev_s[tid]);
        if ((tid & 31) == 0) denom_s[tid >> 5] = v;
    }
    __syncthreads();

    // Phase B: weighted fp16 tail gather. Warp w -> hop (w>>2), 8 memories
    // (2 per halfwarp x 4). Lane ll holds dims [4ll..4ll+3] (one uint2 = 4 halfs).
    const int hop = w >> 2;
    const int wq  = w & 3;
    const float inv = 1.0f / denom_s[hop];

    float4 a = make_float4(0.0f, 0.0f, 0.0f, 0.0f);
    #pragma unroll
    for (int p = 0; p < 4; ++p) {
        const int m  = hop * N_MEM + wq * 8 + 2 * p + half;
        const int ti = st_s[m];
        const float pi = ev_s[m] * inv;
        const uint2 d = g_eth[ti * 16 + ll];
        const float2 f01 = __half22float2(*reinterpret_cast<const __half2*>(&d.x));
        const float2 f23 = __half22float2(*reinterpret_cast<const __half2*>(&d.y));
        a.x += pi * f01.x;
        a.y += pi * f01.y;
        a.z += pi * f23.x;
        a.w += pi * f23.y;
    }
    a.x += __shfl_xor_sync(0xffffffffu, a.x, 16);
    a.y += __shfl_xor_sync(0xffffffffu, a.y, 16);
    a.z += __shfl_xor_sync(0xffffffffu, a.z, 16);
    a.w += __shfl_xor_sync(0xffffffffu, a.w, 16);
    if (half == 0) {
        atomicAdd(&acc_s[4 * ll + 0], a.x);
        atomicAdd(&acc_s[4 * ll + 1], a.y);
        atomicAdd(&acc_s[4 * ll + 2], a.z);
        atomicAdd(&acc_s[4 * ll + 3], a.w);
    }
    __syncthreads();

    if (tid < 64)
        g_acc[item * DIM + tid] = acc_s[tid];
}

// ---------------------------------------------------------------------------
// K2: user pooling + scoring. One warp per batch row, halfwarp float4 layout.
// ---------------------------------------------------------------------------
__global__ __launch_bounds__(256)
void user_score_kernel(const float* __restrict__ entity_emb,
                       const int*   __restrict__ records_idx,
                       const int*   __restrict__ items,
                       float*       __restrict__ out)
{
    const int warp = (blockIdx.x * blockDim.x + threadIdx.x) >> 5;
    const int lane = threadIdx.x & 31;
    const int half = lane >> 4;
    const int ll   = lane & 15;
    if (warp >= BATCH) return;

    const int* rec = records_idx + warp * HIST;
    const float4* acc4 = reinterpret_cast<const float4*>(g_acc);

    float4 u = make_float4(0.0f, 0.0f, 0.0f, 0.0f);
    #pragma unroll
    for (int i = 0; i < HIST / 2; ++i) {
        const int idx = rec[2 * i + half];
        const float4 a = acc4[idx * (DIM / 4) + ll];
        u.x += a.x; u.y += a.y; u.z += a.z; u.w += a.w;
    }
    u.x += __shfl_xor_sync(0xffffffffu, u.x, 16);
    u.y += __shfl_xor_sync(0xffffffffu, u.y, 16);
    u.z += __shfl_xor_sync(0xffffffffu, u.z, 16);
    u.w += __shfl_xor_sync(0xffffffffu, u.w, 16);

    const int it = items[warp];
    const float4 p = reinterpret_cast<const float4*>(entity_emb)[it * (DIM / 4) + ll];
    float dot = u.x * p.x + u.y * p.y + u.z * p.z + u.w * p.w;
    dot = half_sum16(dot);

    if (lane == 0)
        out[warp] = 1.0f / (1.0f + expf(-dot));
}

// ---------------------------------------------------------------------------
// Launch
// ---------------------------------------------------------------------------
extern "C" void kernel_launch(void* const* d_in, const int* in_sizes, int n_in,
                              void* d_out, int out_size)
{
    const float* entity_emb   = (const float*)d_in[0];
    const float* relation_emb = (const float*)d_in[1];
    const float* W_w          = (const float*)d_in[2];
    const float* W_b          = (const float*)d_in[3];
    const int*   item_ids     = (const int*)d_in[4];
    const int*   heads        = (const int*)d_in[5];
    const int*   relations    = (const int*)d_in[6];
    const int*   tails        = (const int*)d_in[7];
    const int*   records_idx  = (const int*)d_in[8];
    const int*   items        = (const int*)d_in[9];
    float*       out          = (float*)d_out;

    project_kernel<<<1184, 256>>>(entity_emb, relation_emb, W_w);

    item_acc_kernel<<<N_ITEM, 256>>>(entity_emb, W_b,
                                     item_ids, heads, relations, tails);

    const int warps_per_block = 256 / 32;
    const int blocks = (BATCH + warps_per_block - 1) / warps_per_block;
    user_score_kernel<<<blocks, 256>>>(entity_emb, records_idx, items, out);
}